// round 2
// baseline (speedup 1.0000x reference)
#include <cuda_runtime.h>
#include <cuda_bf16.h>

// Problem: loss = -(targets * log_softmax(S)).sum(-1).mean()
// with targets = 0.3*Q + 0.7*I, where Q = exp(S + u + v - log(m+n)) after
// 50 Sinkhorn iterations.
//
// Key identity: the u-update enforces LSE_j(S+u+v) = -log(m+n), and Z
// subtracts log(m+n) AGAIN, so row sums of Q are (m+n)^-2 ~ 3.7e-9.
// Q's total contribution to the scalar loss is ~1.7e-8 absolute on a loss
// of ~6.6 (rel ~2e-9), far below fp32 resolution of the result and the
// 1e-3 tolerance. Hence, to all representable precision:
//
//     loss = 0.7 * mean_i ( log(sum_j exp(S_ij)) - S_ii )
//
// One streaming pass over the 256MB matrix; HBM-bound.

#define NROWS 8192
#define NCOLS 8192

// scratch (allocation-free rule: __device__ globals)
__device__ float g_row_vals[NROWS];

__global__ void __launch_bounds__(256)
row_lse_kernel(const float* __restrict__ S) {
    const int warp_global = (blockIdx.x * blockDim.x + threadIdx.x) >> 5;
    const int lane = threadIdx.x & 31;
    if (warp_global >= NROWS) return;

    const float4* __restrict__ rowp =
        reinterpret_cast<const float4*>(S + (size_t)warp_global * NCOLS);

    // 8192 floats/row = 2048 float4; 64 float4 per lane
    float sum = 0.0f;
    #pragma unroll 8
    for (int k = lane; k < NCOLS / 4; k += 32) {
        float4 v = rowp[k];
        sum += __expf(v.x) + __expf(v.y) + __expf(v.z) + __expf(v.w);
    }

    // warp tree reduce
    #pragma unroll
    for (int off = 16; off > 0; off >>= 1)
        sum += __shfl_down_sync(0xffffffffu, sum, off);

    if (lane == 0) {
        // diagonal element (row just streamed through L2 -> cheap hit)
        float diag = S[(size_t)warp_global * NCOLS + warp_global];
        g_row_vals[warp_global] = __logf(sum) - diag;
    }
}

__global__ void __launch_bounds__(1024)
final_reduce_kernel(float* __restrict__ out) {
    __shared__ float sh[1024];
    const int tid = threadIdx.x;

    float s = 0.0f;
    #pragma unroll
    for (int i = tid; i < NROWS; i += 1024)
        s += g_row_vals[i];
    sh[tid] = s;
    __syncthreads();

    #pragma unroll
    for (int stride = 512; stride > 0; stride >>= 1) {
        if (tid < stride) sh[tid] += sh[tid + stride];
        __syncthreads();
    }

    if (tid == 0) {
        // loss = (1/B) * sum_i 0.7 * (LSE_i - S_ii)
        out[0] = 0.7f * sh[0] / (float)NROWS;
    }
}

extern "C" void kernel_launch(void* const* d_in, const int* in_sizes, int n_in,
                              void* d_out, int out_size) {
    const float* S = (const float*)d_in[0];
    float* out = (float*)d_out;

    // 8192 rows, one warp per row, 8 warps per block -> 1024 blocks
    row_lse_kernel<<<1024, 256>>>(S);
    final_reduce_kernel<<<1, 1024>>>(out);
}

// round 3
// speedup vs baseline: 1.0322x; 1.0322x over previous
#include <cuda_runtime.h>
#include <cuda_bf16.h>

// loss = 0.7 * mean_i( log(sum_j exp(S_ij)) - S_ii )
//
// (Sinkhorn Q term proven negligible in R1: double normalization by log(m+n)
// makes row sums of Q = (m+n)^-2 ~ 3.7e-9; its loss contribution is ~2e-9
// relative — below fp32 resolution. R1 passed with rel_err = 0.0.)
//
// Single fused streaming kernel: one warp per row, 8 rows per block,
// front-batched 8x float4 streaming loads (__ldcs) for MLP=8/thread,
// warp-shfl row reduce, block partial, threadfence + last-block-done
// final reduction in a FIXED order (deterministic, no float atomics).

#define NROWS   8192
#define NCOLS   8192
#define NBLOCKS 1024   // 8 warps (rows) per block

__device__ float        g_block_sums[NBLOCKS];
__device__ unsigned int g_counter = 0;   // reset to 0 by last block each launch

__global__ void __launch_bounds__(256)
fused_loss_kernel(const float* __restrict__ S, float* __restrict__ out) {
    __shared__ float sh_rows[8];
    __shared__ bool  is_last;
    __shared__ float sh_red[256];

    const int wid  = threadIdx.x >> 5;
    const int lane = threadIdx.x & 31;
    const int row  = blockIdx.x * 8 + wid;

    const float4* __restrict__ p =
        reinterpret_cast<const float4*>(S + (size_t)row * NCOLS) + lane;

    // 2048 float4 per row; 64 per lane; 8 batches of 8 in-flight loads
    float sum = 0.0f;
    #pragma unroll
    for (int iter = 0; iter < 8; ++iter) {
        float4 v[8];
        #pragma unroll
        for (int j = 0; j < 8; ++j)
            v[j] = __ldcs(p + (iter * 8 + j) * 32);
        #pragma unroll
        for (int j = 0; j < 8; ++j)
            sum += (__expf(v[j].x) + __expf(v[j].y))
                 + (__expf(v[j].z) + __expf(v[j].w));
    }

    // warp tree reduce
    #pragma unroll
    for (int off = 16; off > 0; off >>= 1)
        sum += __shfl_down_sync(0xffffffffu, sum, off);

    if (lane == 0) {
        float diag = S[(size_t)row * NCOLS + row];
        sh_rows[wid] = __logf(sum) - diag;
    }
    __syncthreads();

    // block partial (fixed order) + signal
    if (threadIdx.x == 0) {
        float bs = 0.0f;
        #pragma unroll
        for (int i = 0; i < 8; ++i) bs += sh_rows[i];
        g_block_sums[blockIdx.x] = bs;
        __threadfence();
        unsigned int t = atomicAdd(&g_counter, 1u);
        is_last = (t == NBLOCKS - 1);
    }
    __syncthreads();

    // last block: deterministic fixed-order reduction of 1024 partials
    if (is_last) {
        __threadfence();  // acquire side: make all partials visible
        float s = 0.0f;
        #pragma unroll
        for (int k = 0; k < 4; ++k)
            s += g_block_sums[threadIdx.x + k * 256];
        sh_red[threadIdx.x] = s;
        __syncthreads();
        #pragma unroll
        for (int st = 128; st > 0; st >>= 1) {
            if (threadIdx.x < st) sh_red[threadIdx.x] += sh_red[threadIdx.x + st];
            __syncthreads();
        }
        if (threadIdx.x == 0) {
            out[0] = 0.7f * sh_red[0] / (float)NROWS;
            g_counter = 0;   // rearm for next graph replay
        }
    }
}

extern "C" void kernel_launch(void* const* d_in, const int* in_sizes, int n_in,
                              void* d_out, int out_size) {
    const float* S = (const float*)d_in[0];
    float* out = (float*)d_out;
    fused_loss_kernel<<<NBLOCKS, 256>>>(S, out);
}

// round 4
// speedup vs baseline: 1.0430x; 1.0104x over previous
#include <cuda_runtime.h>
#include <cuda_bf16.h>

// loss = 0.7 * mean_i( log(sum_j exp(S_ij)) - S_ii )
// (Sinkhorn Q term below fp32 resolution of the scalar; proven R1, rel_err=0.0)
//
// R3: dynamic (ticketed) block-per-row streaming.
//  - 592 persistent blocks = exactly 4/SM on 148 SMs, all resident, no waves.
//  - Each block grabs one row at a time via an atomic ticket: tail imbalance
//    drops from "slowest statically-assigned warp" to <= 1 row (~3.4us).
//  - Whole 32KB row front-issued as 256 threads x 8 independent LDG.128
//    (register budget now allows true MLP=8; R2's regs=32 could not).
//  - Deterministic: each row computed by one block in fixed order; last-done
//    block reduces the 8192 per-row values in fixed order. Counters re-armed
//    for graph replay.

#define NROWS   8192
#define NCOLS   8192
#define NBLK    592     // 148 SMs * 4 blocks

__device__ float        g_row_vals[NROWS];
__device__ unsigned int g_ticket = 0;
__device__ unsigned int g_done   = 0;

__global__ void __launch_bounds__(256)
loss_kernel(const float* __restrict__ S, float* __restrict__ out) {
    __shared__ unsigned int sh_ticket;
    __shared__ float        sh_part[8];
    __shared__ bool         is_last;
    __shared__ float        sh_red[256];

    const int tid  = threadIdx.x;
    const int wid  = tid >> 5;
    const int lane = tid & 31;

    for (;;) {
        if (tid == 0) sh_ticket = atomicAdd(&g_ticket, 1u);
        __syncthreads();
        const unsigned int row = sh_ticket;
        if (row >= NROWS) break;

        const float4* __restrict__ p =
            reinterpret_cast<const float4*>(S + (size_t)row * NCOLS) + tid;

        // whole row in flight: 2048 float4 = 256 threads x 8 loads
        float4 v[8];
        #pragma unroll
        for (int j = 0; j < 8; ++j)
            v[j] = __ldcs(p + j * 256);

        float sum = 0.0f;
        #pragma unroll
        for (int j = 0; j < 8; ++j)
            sum += (__expf(v[j].x) + __expf(v[j].y))
                 + (__expf(v[j].z) + __expf(v[j].w));

        // warp reduce
        #pragma unroll
        for (int off = 16; off > 0; off >>= 1)
            sum += __shfl_down_sync(0xffffffffu, sum, off);
        if (lane == 0) sh_part[wid] = sum;
        __syncthreads();

        if (tid == 0) {
            float tot = 0.0f;
            #pragma unroll
            for (int w = 0; w < 8; ++w) tot += sh_part[w];
            float diag = S[(size_t)row * NCOLS + row];
            g_row_vals[row] = __logf(tot) - diag;
        }
        __syncthreads();   // protect sh_part / sh_ticket reuse
    }

    // all rows this block will ever write are written; publish + count
    __threadfence();
    __syncthreads();
    if (tid == 0) {
        unsigned int t = atomicAdd(&g_done, 1u);
        is_last = (t == NBLK - 1);
    }
    __syncthreads();

    if (is_last) {
        __threadfence();  // acquire: all blocks' row values visible
        // fixed-order reduction: thread t sums rows t, t+256, ...
        float s = 0.0f;
        #pragma unroll
        for (int k = 0; k < NROWS / 256; ++k)
            s += g_row_vals[tid + k * 256];
        sh_red[tid] = s;
        __syncthreads();
        #pragma unroll
        for (int st = 128; st > 0; st >>= 1) {
            if (tid < st) sh_red[tid] += sh_red[tid + st];
            __syncthreads();
        }
        if (tid == 0) {
            out[0] = 0.7f * sh_red[0] / (float)NROWS;
            g_ticket = 0;   // rearm for next graph replay
            g_done   = 0;
        }
    }
}

extern "C" void kernel_launch(void* const* d_in, const int* in_sizes, int n_in,
                              void* d_out, int out_size) {
    const float* S = (const float*)d_in[0];
    float* out = (float*)d_out;
    loss_kernel<<<NBLK, 256>>>(S, out);
}